// round 16
// baseline (speedup 1.0000x reference)
#include <cuda_runtime.h>

#define NBATCH 16
#define NPTS   4096
#define NCTR   1024
#define NNEI   64
#define BNP    (NBATCH*NPTS)   // 65536
#define BSC    (NBATCH*NCTR)   // 16384
#define RAD2   0.04f
#define MTOT   1048576.0f
#define BNEPS  1e-5f
#define FBIG   3.402823466e38f

typedef unsigned long long u64;

// ---------------- scratch (device globals; no runtime allocation) ----------------
__device__ float g_cpos[BSC*3];
__device__ int   g_gi[BSC*NNEI];
__device__ int   g_cnt[BNP];
__device__ int   g_prog[NBATCH];     // FPS progress counter per batch
__device__ float g_z0[BNP*64];
__device__ float g_z1[BNP*128];
__device__ float g_A[BNP*64];
__device__ float g_D[BSC*64];
__device__ float g_zmx[BSC*128];
__device__ float g_zmn[BSC*128];
__device__ float g_p0[256*128];
__device__ float g_p1[256*256];
__device__ float g_pg0[1024*128];
__device__ float g_pg0b[16*128];
__device__ float g_pg1[BSC*256];
__device__ float g_pg1b[256*256];
__device__ float g_ab0[128];
__device__ float g_ab1[256];
__device__ float g_abg0[128];
__device__ float g_abg1[256];

// -------- packed fp32x2 helpers (exact: each half rounds rn, same as scalar) ---
__device__ __forceinline__ u64 pk2(float x) {
    u64 r;
    asm("mov.b64 %0, {%1, %1};" : "=l"(r) : "r"(__float_as_uint(x)));
    return r;
}
__device__ __forceinline__ u64 pk(float lo, float hi) {
    u64 r;
    asm("mov.b64 %0, {%1, %2};" : "=l"(r) : "r"(__float_as_uint(lo)), "r"(__float_as_uint(hi)));
    return r;
}
__device__ __forceinline__ void fma2(u64& d, u64 a, u64 b) {
    asm("fma.rn.f32x2 %0, %1, %2, %0;" : "+l"(d) : "l"(a), "l"(b));
}
__device__ __forceinline__ u64 add2(u64 a, u64 b) {
    u64 d;
    asm("add.rn.f32x2 %0, %1, %2;" : "=l"(d) : "l"(a), "l"(b));
    return d;
}
__device__ __forceinline__ u64 mul2(u64 a, u64 b) {
    u64 d;
    asm("mul.rn.f32x2 %0, %1, %2;" : "=l"(d) : "l"(a), "l"(b));
    return d;
}
__device__ __forceinline__ void upk(float& lo, float& hi, u64 v) {
    unsigned l, h;
    asm("mov.b64 {%0, %1}, %2;" : "=r"(l), "=r"(h) : "l"(v));
    lo = __uint_as_float(l); hi = __uint_as_float(h);
}

// float4-slot swizzle for the h tile (conflict-free LDS.128 across rg lanes)
__device__ __forceinline__ int swz(int k) {
    return (k & ~7) | ((((k >> 2) ^ (k >> 5)) & 1) << 2) | (k & 3);
}

// ---------------- zero counters + progress (3 chunks -> front at slot 4) ----
__global__ void k_zero(int base) {
    int i = base + blockIdx.x * 1024 + threadIdx.x;
    if (i < BNP) g_cnt[i] = 0;
    if (base == 0 && blockIdx.x == 0 && threadIdx.x < NBATCH) g_prog[threadIdx.x] = 0;
}

// ======================= fused front kernel =======================
// blocks 0..15        : FPS (1/batch)  -> publishes g_prog[b] every 64 iters
// blocks 16..1039     : semantic layer0 z0
// blocks 1040..9231   : geo affine A
// blocks 9232..11279  : geo affine D   (spin on g_prog[b] >= s0+8)
// blocks 11280..12303 : radius grouping (spin on g_prog[b] >= 16*sblk+16)
__global__ __launch_bounds__(512) void k_front(const float* __restrict__ pos,
                                               const float* __restrict__ feat,
                                               const float* __restrict__ w0,
                                               const float* __restrict__ b0,
                                               const float* __restrict__ wg0,
                                               const float* __restrict__ bg0) {
    extern __shared__ float sm[];
    int tid = threadIdx.x;

    if (blockIdx.x < 16) {
        // ---------------- FPS (numerics identical to passing R13/R15) ----------
        float* sx = sm;
        float* sy = sm + NPTS;
        float* sz = sm + 2*NPTS;
        __shared__ __align__(16) float rv[16];
        __shared__ unsigned sbest[2];

        int b = blockIdx.x;
        int lane = tid & 31, w = tid >> 5;
        const float* pb = pos + b*NPTS*3;
        for (int i = tid; i < NPTS; i += 512) {
            sx[i] = pb[3*i]; sy[i] = pb[3*i+1]; sz[i] = pb[3*i+2];
        }
        if (tid == 0) { sbest[0] = 0xFFFFFFFFu; sbest[1] = 0xFFFFFFFFu; }
        __syncthreads();

        u64 PX[4], PY[4], PZ[4];
        float d[8];
#pragma unroll
        for (int p = 0; p < 4; p++) {
            int i0 = tid*8 + 2*p, i1 = i0 + 1;
            PX[p] = pk(sx[i0], sx[i1]);
            PY[p] = pk(sy[i0], sy[i1]);
            PZ[p] = pk(sz[i0], sz[i1]);
            d[2*p] = 1e10f; d[2*p+1] = 1e10f;
        }

        int f = 0;
        float* outp = g_cpos + b*NCTR*3;
        for (int s = 0; s < NCTR; s++) {
            float cx = sx[f], cy = sy[f], cz = sz[f];
            if (tid == 0) { outp[3*s] = cx; outp[3*s+1] = cy; outp[3*s+2] = cz; }
            u64 NCX = pk2(-cx), NCY = pk2(-cy), NCZ = pk2(-cz);
#pragma unroll
            for (int p = 0; p < 4; p++) {
                u64 dx = add2(PX[p], NCX);
                u64 dy = add2(PY[p], NCY);
                u64 dz = add2(PZ[p], NCZ);
                u64 t  = mul2(dx, dx);
                fma2(t, dy, dy);
                fma2(t, dz, dz);
                float f0, f1; upk(f0, f1, t);
                d[2*p]   = fminf(d[2*p],   f0);
                d[2*p+1] = fminf(d[2*p+1], f1);
            }
            float tmax = fmaxf(fmaxf(fmaxf(d[0], d[1]), fmaxf(d[2], d[3])),
                               fmaxf(fmaxf(d[4], d[5]), fmaxf(d[6], d[7])));
            unsigned wmu = __reduce_max_sync(0xffffffffu, __float_as_uint(tmax));
            if (lane == 0) rv[w] = __uint_as_float(wmu);
            __syncthreads();                               // bar 1
            float4 r0 = *(const float4*)&rv[0];
            float4 r1 = *(const float4*)&rv[4];
            float4 r2 = *(const float4*)&rv[8];
            float4 r3 = *(const float4*)&rv[12];
            float bm = fmaxf(
                fmaxf(fmaxf(fmaxf(r0.x, r0.y), fmaxf(r0.z, r0.w)),
                      fmaxf(fmaxf(r1.x, r1.y), fmaxf(r1.z, r1.w))),
                fmaxf(fmaxf(fmaxf(r2.x, r2.y), fmaxf(r2.z, r2.w)),
                      fmaxf(fmaxf(r3.x, r3.y), fmaxf(r3.z, r3.w))));
            if (tid == 0) sbest[(s & 1) ^ 1] = 0xFFFFFFFFu;
            if (tmax == bm) {
                int j = 7;
#pragma unroll
                for (int jj = 6; jj >= 0; jj--) if (d[jj] == tmax) j = jj;
                atomicMin(&sbest[s & 1], (unsigned)(tid*8 + j));
            }
            __syncthreads();                               // bar 2
            f = (int)sbest[s & 1];
            // publish progress every 64 iterations (centroids 0..s are written)
            if ((s & 63) == 63 && tid == 0) {
                __threadfence();
                atomicExch(&g_prog[b], s + 1);
            }
        }
    } else if (blockIdx.x < 16 + 1024) {
        // ---------------- semantic layer0: z0 = feat @ w0^T + b0 (64 rows) ----------
        float* wsh = sm;            // 64x64  [cc][c]
        float* fsh = sm + 4096;     // 64x68  [cc][row]
        int row0 = (blockIdx.x - 16) * 64;
        for (int idx = tid; idx < 4096; idx += 512) {
            int c = idx >> 6, cc = idx & 63;
            wsh[cc*64 + c] = w0[c*64 + cc];
        }
        for (int idx = tid; idx < 4096; idx += 512) {
            int r = idx >> 6, cc = idx & 63;
            fsh[cc*68 + r] = feat[(row0 + r)*64 + cc];
        }
        __syncthreads();
        int tx = tid & 31, ty = tid >> 5;   // rows = ty*4+i, ch = tx*2+{0,1}
        u64 acc[4];
#pragma unroll
        for (int i = 0; i < 4; i++) acc[i] = 0ull;
        const u64* w64 = (const u64*)wsh;
#pragma unroll 4
        for (int cc = 0; cc < 64; cc++) {
            u64 wv = w64[cc*32 + tx];
            float4 ha = *(float4*)&fsh[cc*68 + ty*4];
            fma2(acc[0], pk2(ha.x), wv);
            fma2(acc[1], pk2(ha.y), wv);
            fma2(acc[2], pk2(ha.z), wv);
            fma2(acc[3], pk2(ha.w), wv);
        }
#pragma unroll
        for (int i = 0; i < 4; i++) {
            int r = row0 + ty*4 + i, c = tx*2;
            float lo, hi; upk(lo, hi, acc[i]);
            float2 vv; vv.x = lo + b0[c]; vv.y = hi + b0[c+1];
            *(float2*)&g_z0[r*64 + c] = vv;
        }
    } else if (blockIdx.x < 9232) {
        // ---------------- geo affine A (8 rows) ----------------
        float* u = sm;              // 192 floats
        if (tid < 192) {
            int c = tid/3, i = tid - 3*c;
            u[tid] = wg0[c*6 + i] + wg0[c*6 + 3 + i];
        }
        __syncthreads();
        int r = (blockIdx.x - 1040)*8 + (tid >> 6), c = tid & 63;
        float x = pos[r*3], y = pos[r*3+1], z = pos[r*3+2];
        g_A[r*64 + c] = u[c*3]*x + u[c*3+1]*y + u[c*3+2]*z + bg0[c];
    } else if (blockIdx.x < 11280) {
        // ---------------- geo affine D (8 centers), waits for FPS progress ---------
        float* v = sm;              // 192 floats
        if (tid < 192) { int c = tid/3, i = tid - 3*c; v[tid] = wg0[c*6 + 3 + i]; }
        int db = blockIdx.x - 9232;            // 0..2047
        int s0 = db*8;
        int b = s0 >> 10;
        int need = (s0 & 1023) + 8;
        if (tid == 0) {
            while (atomicAdd(&g_prog[b], 0) < need) { __nanosleep(64); }
        }
        __syncthreads();
        __threadfence();
        int s = s0 + (tid >> 6), c = tid & 63;
        float x = g_cpos[s*3], y = g_cpos[s*3+1], z = g_cpos[s*3+2];
        g_D[s*64 + c] = v[c*3]*x + v[c*3+1]*y + v[c*3+2]*z;
    } else {
        // ---------------- radius grouping (16 centers), waits for FPS progress -----
        float4* smq = (float4*)sm;             // 4608 float4, pad-per-8 layout
        int* sel = (int*)(smq + 4608);         // 64 ints
        __shared__ int s_warp[16];
        __shared__ int s_tot;
        int gb = blockIdx.x - 11280;           // 0..1023
        int b = gb >> 6;
        int sblk = gb & 63;
        int need = sblk*16 + 16;
        const float* pb = pos + b*NPTS*3;
        for (int i = tid; i < NPTS; i += 512) {
            float x = pb[3*i], y = pb[3*i+1], z = pb[3*i+2];
            smq[i + (i >> 3)] = make_float4(x, y, z, (x*x + y*y) + z*z);
        }
        if (tid == 0) {
            while (atomicAdd(&g_prog[b], 0) < need) { __nanosleep(64); }
        }
        __syncthreads();
        __threadfence();

        const float4* myp = smq + tid*9;       // 8 contiguous padded slots
        int lane = tid & 31, w = tid >> 5;
        for (int cs = 0; cs < 16; cs++) {
            int s = sblk*16 + cs;
            int cidx = b*NCTR + s;
            float cx = g_cpos[3*cidx], cy = g_cpos[3*cidx+1], cz = g_cpos[3*cidx+2];
            float cc = (cx*cx + cy*cy) + cz*cz;

            unsigned mask8 = 0; int mycnt = 0;
#pragma unroll
            for (int jj = 0; jj < 8; jj++) {
                float4 q = myp[jj];
                float dot = cx*q.x + cy*q.y + cz*q.z;
                float sq  = (cc - 2.0f*dot) + q.w;
                if (!(sq > RAD2)) { mask8 |= (1u << jj); mycnt++; }
            }
            int inc = mycnt;
#pragma unroll
            for (int o = 1; o < 32; o <<= 1) {
                int vv = __shfl_up_sync(0xffffffffu, inc, o);
                if (lane >= o) inc += vv;
            }
            if (lane == 31) s_warp[w] = inc;
            __syncthreads();
            int woff = 0;
            for (int i = 0; i < w; i++) woff += s_warp[i];
            int excl = woff + inc - mycnt;
            int p = excl;
            unsigned m = mask8;
            while (m && p < 64) {
                int jj = __ffs(m) - 1; m &= m - 1;
                sel[p++] = tid*8 + jj;
            }
            if (tid == 0) { int t2 = 0; for (int i = 0; i < 16; i++) t2 += s_warp[i]; s_tot = t2; }
            __syncthreads();
            int tot = s_tot; if (tot > 64) tot = 64;
            if (tid >= tot && tid < 64) sel[tid] = sel[0];   // pad with first in-ball idx
            __syncthreads();
            if (tid < 64) {
                int n = sel[tid];
                g_gi[cidx*64 + tid] = n;
                atomicAdd(&g_cnt[b*NPTS + n], 1);
            }
            __syncthreads();
        }
    }
}

// ---------------- 3b) count-weighted stats of z0 ----------------
__global__ __launch_bounds__(256) void k_stat0() {
    __shared__ float red[512];
    int tid = threadIdx.x;
    int c = tid & 63, rg = tid >> 6;     // rg in 0..3
    int r0 = blockIdx.x * 256;
    float s1 = 0.f, s2 = 0.f;
    for (int r = r0 + rg; r < r0 + 256; r += 4) {
        float w = (float)g_cnt[r];
        float z = g_z0[r*64 + c];
        s1 += w*z; s2 += w*z*z;
    }
    red[tid] = s1; red[256 + tid] = s2;
    __syncthreads();
    if (tid < 64) {
        float a = red[tid] + red[tid+64] + red[tid+128] + red[tid+192];
        float b = red[256+tid] + red[256+tid+64] + red[256+tid+128] + red[256+tid+192];
        g_p0[blockIdx.x*128 + tid] = a;
        g_p0[blockIdx.x*128 + 64 + tid] = b;
    }
}

// ---------------- BN finalize on device-global partials (sel picks buffers) ----------
__global__ void k_fin(int sel, int nb,
                      const float* __restrict__ gm, const float* __restrict__ bt) {
    int c = threadIdx.x;
    const float* part; float* ab; int C;
    if (sel == 0)      { part = g_p0;   ab = g_ab0;  C = 64;  }
    else if (sel == 1) { part = g_p1;   ab = g_ab1;  C = 128; }
    else if (sel == 2) { part = g_pg0b; ab = g_abg0; C = 64;  }
    else               { part = g_pg1b; ab = g_abg1; C = 128; }
    float s1 = 0.f, s2 = 0.f;
    for (int r = 0; r < nb; r++) { s1 += part[r*2*C + c]; s2 += part[r*2*C + C + c]; }
    float m = s1 / MTOT;
    float v = s2 / MTOT - m*m;
    float a = gm[c] * rsqrtf(v + BNEPS);
    ab[c] = a; ab[C + c] = bt[c] - m*a;
}

// ---------------- partial reduce for geo layer1 stats (pg1 -> pg1b) ----------------
__global__ void k_red() {
    int c = threadIdx.x;               // 256
    float s = 0.f;
    int r0 = blockIdx.x * 64;
    for (int r = 0; r < 64; r++) s += g_pg1[(r0 + r)*256 + c];
    g_pg1b[blockIdx.x*256 + c] = s;
}

// ---------------- partial reduce for geo layer0 stats (pg0 -> pg0b) ----------------
__global__ void k_redg0() {
    int c = threadIdx.x;               // 128
    float s = 0.f;
    int r0 = blockIdx.x * 64;
    for (int r = 0; r < 64; r++) s += g_pg0[(r0 + r)*128 + c];
    g_pg0b[blockIdx.x*128 + c] = s;
}

// ---------------- 3c) h0 = relu(a0*z0+e0); z1 = h0 @ w1^T + b1 ----------------
__global__ __launch_bounds__(256) void k_z1(const float* __restrict__ w1,
                                            const float* __restrict__ b1) {
    extern __shared__ float sm[];
    float* wsh2 = sm;             // 128x65 [c][cc]  = 33280 B
    float* hsh  = sm + 8320;      // 64x68  [cc][swz(row)] = 17408 B
    __shared__ float a0[64], e0[64];
    int tid = threadIdx.x;
    if (tid < 64) { a0[tid] = g_ab0[tid]; e0[tid] = g_ab0[64 + tid]; }
    int row0 = blockIdx.x * 64;
    for (int idx = tid; idx < 8192; idx += 256) {
        int c = idx >> 6, cc = idx & 63;
        wsh2[c*65 + cc] = w1[idx];
    }
    __syncthreads();
    for (int idx = tid; idx < 4096; idx += 256) {
        int r = idx >> 6, cc = idx & 63;
        float z = g_z0[(row0 + r)*64 + cc];
        hsh[cc*68 + swz(r)] = fmaxf(0.f, a0[cc]*z + e0[cc]);
    }
    __syncthreads();

    int rg = tid & 7;      // rows k = rg*8 + i
    int cg = tid >> 3;     // channels c = cg*4 + {0..3}
    int sw4 = (rg >> 2) << 2;
    const float* pLO = hsh + rg*8 + sw4;
    const float* pHI = hsh + rg*8 + (4 - sw4);
    const float* pw  = wsh2 + cg*4*65;
    u64 acc[8][2];
#pragma unroll
    for (int i = 0; i < 8; i++) { acc[i][0] = 0ull; acc[i][1] = 0ull; }
#pragma unroll 4
    for (int cc = 0; cc < 64; cc++) {
        float4 ha = *(const float4*)&pLO[cc*68];
        float4 hb = *(const float4*)&pHI[cc*68];
        float w0v = pw[cc], w1v = pw[65 + cc], w2v = pw[130 + cc], w3v = pw[195 + cc];
        u64 wp0 = pk(w0v, w1v), wp1 = pk(w2v, w3v);
        float hv[8] = {ha.x, ha.y, ha.z, ha.w, hb.x, hb.y, hb.z, hb.w};
#pragma unroll
        for (int i = 0; i < 8; i++) {
            u64 h2 = pk2(hv[i]);
            fma2(acc[i][0], h2, wp0);
            fma2(acc[i][1], h2, wp1);
        }
    }
#pragma unroll
    for (int i = 0; i < 8; i++) {
        int r = row0 + rg*8 + i, c = cg*4;
        float l0, h0v, l1, h1v;
        upk(l0, h0v, acc[i][0]); upk(l1, h1v, acc[i][1]);
        float4 v;
        v.x = l0 + b1[c];   v.y = h0v + b1[c+1];
        v.z = l1 + b1[c+2]; v.w = h1v + b1[c+3];
        *(float4*)&g_z1[r*128 + c] = v;
    }
}

// ---------------- 3d) count-weighted stats of z1 ----------------
__global__ __launch_bounds__(256) void k_stat1() {
    __shared__ float red[512];
    int tid = threadIdx.x;
    int c = tid & 127, rg = tid >> 7;   // rg in 0..1
    int r0 = blockIdx.x * 256;
    float s1 = 0.f, s2 = 0.f;
    for (int r = r0 + rg; r < r0 + 256; r += 2) {
        float w = (float)g_cnt[r];
        float z = g_z1[r*128 + c];
        s1 += w*z; s2 += w*z*z;
    }
    red[tid] = s1; red[256 + tid] = s2;
    __syncthreads();
    if (tid < 128) {
        g_p1[blockIdx.x*256 + tid]       = red[tid] + red[tid + 128];
        g_p1[blockIdx.x*256 + 128 + tid] = red[256 + tid] + red[256 + tid + 128];
    }
}

// ---------------- 4b) geo layer0 pair stats (128 thr: even/odd cs halves) ----------
__global__ __launch_bounds__(128) void k_g0stats() {
    __shared__ float sS1[128], sS2[128];
    int tid = threadIdx.x;
    int c = tid & 63, half = tid >> 6;
    int b = blockIdx.x >> 6;
    int s0 = (blockIdx.x & 63) * 16;
    float S1 = 0.f, S2 = 0.f;
    for (int cs = half; cs < 16; cs += 2) {
        int cidx = b*NCTR + s0 + cs;
        const int* g = g_gi + cidx*64;
        float sA = 0.f, sA2 = 0.f;
#pragma unroll 8
        for (int k = 0; k < 64; k++) {
            int n = g[k];
            float a = g_A[(b*NPTS + n)*64 + c];
            sA += a; sA2 += a*a;
        }
        float d = g_D[cidx*64 + c];
        S1 += sA - 64.f*d;
        S2 += sA2 - 2.f*d*sA + 64.f*d*d;
    }
    sS1[tid] = S1; sS2[tid] = S2;
    __syncthreads();
    if (tid < 64) {
        g_pg0[blockIdx.x*128 + tid]      = sS1[tid] + sS1[64 + tid];
        g_pg0[blockIdx.x*128 + 64 + tid] = sS2[tid] + sS2[64 + tid];
    }
}

// ---------------- 5) big geo kernel: 2 centers / 256-thread block ----------------
__global__ __launch_bounds__(256, 2) void k_geo(const float* __restrict__ wg1,
                                                const float* __restrict__ bg1) {
    extern __shared__ float sm[];
    float* wsh2 = sm;                               // 128x65 = 33280 B
    int tid = threadIdx.x;
    int half = tid >> 7;                            // 0 or 1
    int t = tid & 127;
    float* hsh = sm + 8320 + half*4352;             // 64x68 per half
    __shared__ float dsh[128], a0[64], e0[64];
    int cidx = blockIdx.x*2 + half;
    int b = cidx >> 10;
    for (int idx = tid; idx < 8192; idx += 256) {
        int c = idx >> 6, cc = idx & 63;
        wsh2[c*65 + cc] = wg1[idx];
    }
    if (tid < 64) { a0[tid] = g_abg0[tid]; e0[tid] = g_abg0[64 + tid]; }
    if (t < 64) dsh[half*64 + t] = g_D[cidx*64 + t];
    __syncthreads();
    for (int idx = t; idx < 4096; idx += 128) {
        int k = idx >> 6, c = idx & 63;
        int n = g_gi[cidx*64 + k];
        float z = g_A[(b*NPTS + n)*64 + c] - dsh[half*64 + c];
        hsh[c*68 + swz(k)] = fmaxf(0.f, a0[c]*z + e0[c]);
    }
    __syncthreads();

    int rg = t & 7;      // rows k = rg*8 + i
    int cg = t >> 3;     // ch   c = cg*8 + p*2 + {0,1}
    int sw4 = (rg >> 2) << 2;
    const float* pLO = hsh + rg*8 + sw4;
    const float* pHI = hsh + rg*8 + (4 - sw4);
    const float* pw  = wsh2 + cg*8*65;
    u64 acc[8][4];
#pragma unroll
    for (int i = 0; i < 8; i++)
#pragma unroll
        for (int p = 0; p < 4; p++) acc[i][p] = 0ull;
#pragma unroll 2
    for (int cc = 0; cc < 64; cc++) {
        float4 ha = *(const float4*)&pLO[cc*68];
        float4 hb = *(const float4*)&pHI[cc*68];
        float ws0 = pw[cc],        ws1 = pw[65 + cc];
        float ws2 = pw[130 + cc],  ws3 = pw[195 + cc];
        float ws4 = pw[260 + cc],  ws5 = pw[325 + cc];
        float ws6 = pw[390 + cc],  ws7 = pw[455 + cc];
        u64 wp0 = pk(ws0, ws1), wp1 = pk(ws2, ws3);
        u64 wp2 = pk(ws4, ws5), wp3 = pk(ws6, ws7);
        float hv[8] = {ha.x, ha.y, ha.z, ha.w, hb.x, hb.y, hb.z, hb.w};
#pragma unroll
        for (int i = 0; i < 8; i++) {
            u64 h2 = pk2(hv[i]);
            fma2(acc[i][0], h2, wp0);
            fma2(acc[i][1], h2, wp1);
            fma2(acc[i][2], h2, wp2);
            fma2(acc[i][3], h2, wp3);
        }
    }

    // epilogue, streamed per accumulator column p (two channels at a time)
#pragma unroll
    for (int p = 0; p < 4; p++) {
        float lo[8], hi[8];
#pragma unroll
        for (int i = 0; i < 8; i++) upk(lo[i], hi[i], acc[i][p]);
#pragma unroll
        for (int jj = 0; jj < 2; jj++) {
            int c = cg*8 + p*2 + jj;
            float bb = bg1[c];
            float mx = -FBIG, mn = FBIG, s1 = 0.f, s2 = 0.f;
#pragma unroll
            for (int i = 0; i < 8; i++) {
                float z = (jj ? hi[i] : lo[i]) + bb;
                mx = fmaxf(mx, z); mn = fminf(mn, z);
                s1 += z; s2 += z*z;
            }
#pragma unroll
            for (int o = 1; o < 8; o <<= 1) {
                mx = fmaxf(mx, __shfl_xor_sync(0xffffffffu, mx, o));
                mn = fminf(mn, __shfl_xor_sync(0xffffffffu, mn, o));
                s1 += __shfl_xor_sync(0xffffffffu, s1, o);
                s2 += __shfl_xor_sync(0xffffffffu, s2, o);
            }
            if (rg == 0) {
                g_zmx[cidx*128 + c] = mx;
                g_zmn[cidx*128 + c] = mn;
                g_pg1[cidx*256 + c] = s1;
                g_pg1[cidx*256 + 128 + c] = s2;
            }
        }
    }
}

// ---------------- 7a) semantic output: gather-max of pre-BN z1, monotone BN+relu ----
__global__ __launch_bounds__(128) void k_outsem(float* __restrict__ out) {
    int c = threadIdx.x;
    int cidx = blockIdx.x;
    int b = cidx >> 10;
    float a = g_ab1[c], e = g_ab1[128 + c];
    const int* g = g_gi + cidx*64;
    bool posa = (a >= 0.f);
    float m = posa ? -FBIG : FBIG;
#pragma unroll 4
    for (int k = 0; k < 64; k++) {
        int n = g[k];
        float z = g_z1[(b*NPTS + n)*128 + c];
        m = posa ? fmaxf(m, z) : fminf(m, z);
    }
    out[cidx*128 + c] = fmaxf(0.f, a*m + e);
}

// ---------------- 7b) geo output from zmax/zmin ----------------
__global__ __launch_bounds__(128) void k_outgeo(float* __restrict__ out) {
    int c = threadIdx.x;
    int cidx = blockIdx.x;
    float a = g_abg1[c], e = g_abg1[128 + c];
    float m = (a >= 0.f) ? g_zmx[cidx*128 + c] : g_zmn[cidx*128 + c];
    out[(BSC + cidx)*128 + c] = fmaxf(0.f, a*m + e);
}

// =============================== host ===============================
extern "C" void kernel_launch(void* const* d_in, const int* in_sizes, int n_in,
                              void* d_out, int out_size) {
    const float* pos  = (const float*)d_in[0];
    const float* feat = (const float*)d_in[1];
    const float* w0   = (const float*)d_in[2];
    const float* b0   = (const float*)d_in[3];
    const float* gm0  = (const float*)d_in[4];
    const float* bt0  = (const float*)d_in[5];
    const float* w1   = (const float*)d_in[6];
    const float* b1   = (const float*)d_in[7];
    const float* gm1  = (const float*)d_in[8];
    const float* bt1  = (const float*)d_in[9];
    const float* wg0  = (const float*)d_in[10];
    const float* bg0  = (const float*)d_in[11];
    const float* gmg0 = (const float*)d_in[12];
    const float* btg0 = (const float*)d_in[13];
    const float* wg1  = (const float*)d_in[14];
    const float* bg1  = (const float*)d_in[15];
    const float* gmg1 = (const float*)d_in[16];
    const float* btg1 = (const float*)d_in[17];
    float* out = (float*)d_out;

    cudaFuncSetAttribute(k_front, cudaFuncAttributeMaxDynamicSharedMemorySize, 74240);
    cudaFuncSetAttribute(k_z1,    cudaFuncAttributeMaxDynamicSharedMemorySize, 50688);
    cudaFuncSetAttribute(k_geo,   cudaFuncAttributeMaxDynamicSharedMemorySize, 68096);

    k_zero<<<22, 1024>>>(0);                          // slot 1 (also zeroes g_prog)
    k_zero<<<22, 1024>>>(22528);                      // slot 2
    k_zero<<<20, 1024>>>(45056);                      // slot 3
    k_front<<<12304, 512, 74240>>>(pos, feat, w0, b0, wg0, bg0);  // slot 4 -> ncu

    // semantic branch
    k_stat0<<<256, 256>>>();
    k_fin<<<1, 64>>>(0, 256, gm0, bt0);
    k_z1<<<BNP/64, 256, 50688>>>(w1, b1);
    k_stat1<<<256, 256>>>();
    k_fin<<<1, 128>>>(1, 256, gm1, bt1);

    // geo branch
    k_g0stats<<<1024, 128>>>();
    k_redg0<<<16, 128>>>();
    k_fin<<<1, 64>>>(2, 16, gmg0, btg0);
    k_geo<<<BSC/2, 256, 68096>>>(wg1, bg1);
    k_red<<<256, 256>>>();
    k_fin<<<1, 128>>>(3, 256, gmg1, btg1);

    // outputs
    k_outsem<<<BSC, 128>>>(out);
    k_outgeo<<<BSC, 128>>>(out);
    (void)in_sizes; (void)n_in; (void)out_size;
}

// round 17
// speedup vs baseline: 1.0909x; 1.0909x over previous
#include <cuda_runtime.h>

#define NBATCH 16
#define NPTS   4096
#define NCTR   1024
#define NNEI   64
#define BNP    (NBATCH*NPTS)   // 65536
#define BSC    (NBATCH*NCTR)   // 16384
#define RAD2   0.04f
#define MTOT   1048576.0f
#define BNEPS  1e-5f
#define FBIG   3.402823466e38f

typedef unsigned long long u64;

// ---------------- scratch (device globals; no runtime allocation) ----------------
__device__ float g_cpos[BSC*3];
__device__ int   g_gi[BSC*NNEI];
__device__ int   g_cnt[BNP];
__device__ float g_z0[BNP*64];
__device__ float g_z1[BNP*128];
__device__ float g_A[BNP*64];
__device__ float g_D[BSC*64];
__device__ float g_zmx[BSC*128];
__device__ float g_zmn[BSC*128];
__device__ float g_p0[256*128];
__device__ float g_p1[256*256];
__device__ float g_pg0[1024*128];
__device__ float g_pg0b[16*128];
__device__ float g_pg1[BSC*256];
__device__ float g_pg1b[256*256];
__device__ float g_ab0[128];
__device__ float g_ab1[256];
__device__ float g_abg0[128];
__device__ float g_abg1[256];

// -------- packed fp32x2 helpers (exact: each half rounds rn, same as scalar) ---
__device__ __forceinline__ u64 pk2(float x) {
    u64 r;
    asm("mov.b64 %0, {%1, %1};" : "=l"(r) : "r"(__float_as_uint(x)));
    return r;
}
__device__ __forceinline__ u64 pk(float lo, float hi) {
    u64 r;
    asm("mov.b64 %0, {%1, %2};" : "=l"(r) : "r"(__float_as_uint(lo)), "r"(__float_as_uint(hi)));
    return r;
}
__device__ __forceinline__ void fma2(u64& d, u64 a, u64 b) {
    asm("fma.rn.f32x2 %0, %1, %2, %0;" : "+l"(d) : "l"(a), "l"(b));
}
__device__ __forceinline__ u64 add2(u64 a, u64 b) {
    u64 d;
    asm("add.rn.f32x2 %0, %1, %2;" : "=l"(d) : "l"(a), "l"(b));
    return d;
}
__device__ __forceinline__ u64 mul2(u64 a, u64 b) {
    u64 d;
    asm("mul.rn.f32x2 %0, %1, %2;" : "=l"(d) : "l"(a), "l"(b));
    return d;
}
__device__ __forceinline__ void upk(float& lo, float& hi, u64 v) {
    unsigned l, h;
    asm("mov.b64 {%0, %1}, %2;" : "=r"(l), "=r"(h) : "l"(v));
    lo = __uint_as_float(l); hi = __uint_as_float(h);
}

// float4-slot swizzle for the h tile (conflict-free LDS.128 across rg lanes)
__device__ __forceinline__ int swz(int k) {
    return (k & ~7) | ((((k >> 2) ^ (k >> 5)) & 1) << 2) | (k & 3);
}

// ---------------- zero the multiplicity counters (3 chunks -> front at slot 4) -----
__global__ void k_zero(int base) {
    int i = base + blockIdx.x * 1024 + threadIdx.x;
    if (i < BNP) g_cnt[i] = 0;
}

// ======================= fused front kernel (R13 structure) =======================
// blocks 0..15 : FPS (1/batch); 16..1039 : z0 tiles; 1040..9231 : geo A.
__global__ __launch_bounds__(512) void k_front(const float* __restrict__ pos,
                                               const float* __restrict__ feat,
                                               const float* __restrict__ w0,
                                               const float* __restrict__ b0,
                                               const float* __restrict__ wg0,
                                               const float* __restrict__ bg0) {
    extern __shared__ float sm[];
    int tid = threadIdx.x;

    if (blockIdx.x < 16) {
        // ---------------- FPS ----------------
        float* sx = sm;
        float* sy = sm + NPTS;
        float* sz = sm + 2*NPTS;
        __shared__ __align__(16) float rv[16];
        __shared__ unsigned sbest[2];

        int b = blockIdx.x;
        int lane = tid & 31, w = tid >> 5;
        const float* pb = pos + b*NPTS*3;
        for (int i = tid; i < NPTS; i += 512) {
            sx[i] = pb[3*i]; sy[i] = pb[3*i+1]; sz[i] = pb[3*i+2];
        }
        if (tid == 0) { sbest[0] = 0xFFFFFFFFu; sbest[1] = 0xFFFFFFFFu; }
        __syncthreads();

        u64 PX[4], PY[4], PZ[4];
        float d[8];
#pragma unroll
        for (int p = 0; p < 4; p++) {
            int i0 = tid*8 + 2*p, i1 = i0 + 1;
            PX[p] = pk(sx[i0], sx[i1]);
            PY[p] = pk(sy[i0], sy[i1]);
            PZ[p] = pk(sz[i0], sz[i1]);
            d[2*p] = 1e10f; d[2*p+1] = 1e10f;
        }

        int f = 0;
        float* outp = g_cpos + b*NCTR*3;
        for (int s = 0; s < NCTR; s++) {
            float cx = sx[f], cy = sy[f], cz = sz[f];
            if (tid == 0) { outp[3*s] = cx; outp[3*s+1] = cy; outp[3*s+2] = cz; }
            u64 NCX = pk2(-cx), NCY = pk2(-cy), NCZ = pk2(-cz);
#pragma unroll
            for (int p = 0; p < 4; p++) {
                u64 dx = add2(PX[p], NCX);
                u64 dy = add2(PY[p], NCY);
                u64 dz = add2(PZ[p], NCZ);
                u64 t  = mul2(dx, dx);
                fma2(t, dy, dy);
                fma2(t, dz, dz);
                float f0, f1; upk(f0, f1, t);
                d[2*p]   = fminf(d[2*p],   f0);
                d[2*p+1] = fminf(d[2*p+1], f1);
            }
            float tmax = fmaxf(fmaxf(fmaxf(d[0], d[1]), fmaxf(d[2], d[3])),
                               fmaxf(fmaxf(d[4], d[5]), fmaxf(d[6], d[7])));
            unsigned wmu = __reduce_max_sync(0xffffffffu, __float_as_uint(tmax));
            if (lane == 0) rv[w] = __uint_as_float(wmu);
            __syncthreads();                               // bar 1
            float4 r0 = *(const float4*)&rv[0];
            float4 r1 = *(const float4*)&rv[4];
            float4 r2 = *(const float4*)&rv[8];
            float4 r3 = *(const float4*)&rv[12];
            float bm = fmaxf(
                fmaxf(fmaxf(fmaxf(r0.x, r0.y), fmaxf(r0.z, r0.w)),
                      fmaxf(fmaxf(r1.x, r1.y), fmaxf(r1.z, r1.w))),
                fmaxf(fmaxf(fmaxf(r2.x, r2.y), fmaxf(r2.z, r2.w)),
                      fmaxf(fmaxf(r3.x, r3.y), fmaxf(r3.z, r3.w))));
            if (tid == 0) sbest[(s & 1) ^ 1] = 0xFFFFFFFFu;
            if (tmax == bm) {
                int j = 7;
#pragma unroll
                for (int jj = 6; jj >= 0; jj--) if (d[jj] == tmax) j = jj;
                atomicMin(&sbest[s & 1], (unsigned)(tid*8 + j));
            }
            __syncthreads();                               // bar 2
            f = (int)sbest[s & 1];
        }
    } else if (blockIdx.x < 16 + 1024) {
        // ---------------- semantic layer0: z0 = feat @ w0^T + b0 (64 rows) ----------
        float* wsh = sm;            // 64x64  [cc][c]
        float* fsh = sm + 4096;     // 64x68  [cc][row]
        int row0 = (blockIdx.x - 16) * 64;
        for (int idx = tid; idx < 4096; idx += 512) {
            int c = idx >> 6, cc = idx & 63;
            wsh[cc*64 + c] = w0[c*64 + cc];
        }
        for (int idx = tid; idx < 4096; idx += 512) {
            int r = idx >> 6, cc = idx & 63;
            fsh[cc*68 + r] = feat[(row0 + r)*64 + cc];
        }
        __syncthreads();
        int tx = tid & 31, ty = tid >> 5;   // rows = ty*4+i, ch = tx*2+{0,1}
        u64 acc[4];
#pragma unroll
        for (int i = 0; i < 4; i++) acc[i] = 0ull;
        const u64* w64 = (const u64*)wsh;
#pragma unroll 4
        for (int cc = 0; cc < 64; cc++) {
            u64 wv = w64[cc*32 + tx];
            float4 ha = *(float4*)&fsh[cc*68 + ty*4];
            fma2(acc[0], pk2(ha.x), wv);
            fma2(acc[1], pk2(ha.y), wv);
            fma2(acc[2], pk2(ha.z), wv);
            fma2(acc[3], pk2(ha.w), wv);
        }
#pragma unroll
        for (int i = 0; i < 4; i++) {
            int r = row0 + ty*4 + i, c = tx*2;
            float lo, hi; upk(lo, hi, acc[i]);
            float2 vv; vv.x = lo + b0[c]; vv.y = hi + b0[c+1];
            *(float2*)&g_z0[r*64 + c] = vv;
        }
    } else {
        // ---------------- geo affine A (8 rows) ----------------
        float* u = sm;              // 192 floats
        if (tid < 192) {
            int c = tid/3, i = tid - 3*c;
            u[tid] = wg0[c*6 + i] + wg0[c*6 + 3 + i];
        }
        __syncthreads();
        int r = (blockIdx.x - 1040)*8 + (tid >> 6), c = tid & 63;
        float x = pos[r*3], y = pos[r*3+1], z = pos[r*3+2];
        g_A[r*64 + c] = u[c*3]*x + u[c*3+1]*y + u[c*3+2]*z + bg0[c];
    }
}

// ---------------- 2) Radius-ball grouping (R13 proven version) ----------------
__global__ __launch_bounds__(128) void k_group(const float* __restrict__ pos) {
    extern __shared__ float4 smq[];        // 4224 float4 (= 128*33, padded)
    int* sel = (int*)(smq + 4224);         // 64 ints
    __shared__ int s_warp[4];
    __shared__ int s_tot;

    int b = blockIdx.y;
    int tid = threadIdx.x;                 // 128 threads
    const float* pb = pos + b*NPTS*3;
    for (int i = tid; i < NPTS; i += 128) {
        float x = pb[3*i], y = pb[3*i+1], z = pb[3*i+2];
        smq[i + (i >> 5)] = make_float4(x, y, z, (x*x + y*y) + z*z);
    }
    __syncthreads();

    const float4* myp = smq + tid*33;
    for (int cs = 0; cs < 16; cs++) {
        int s = blockIdx.x*16 + cs;
        int cidx = b*NCTR + s;
        float cx = g_cpos[3*cidx], cy = g_cpos[3*cidx+1], cz = g_cpos[3*cidx+2];
        float cc = (cx*cx + cy*cy) + cz*cz;

        int base = tid*32;
        unsigned mask32 = 0; int mycnt = 0;
#pragma unroll 4
        for (int jj = 0; jj < 32; jj++) {
            float4 q = myp[jj];
            float dot = cx*q.x + cy*q.y + cz*q.z;
            float sq  = (cc - 2.0f*dot) + q.w;
            if (!(sq > RAD2)) { mask32 |= (1u << jj); mycnt++; }
        }
        int lane = tid & 31, w = tid >> 5;
        int inc = mycnt;
#pragma unroll
        for (int o = 1; o < 32; o <<= 1) {
            int v = __shfl_up_sync(0xffffffffu, inc, o);
            if (lane >= o) inc += v;
        }
        if (lane == 31) s_warp[w] = inc;
        __syncthreads();
        int woff = 0;
        for (int i = 0; i < w; i++) woff += s_warp[i];
        int excl = woff + inc - mycnt;
        int p = excl;
        unsigned m = mask32;
        while (m && p < 64) {
            int jj = __ffs(m) - 1; m &= m - 1;
            sel[p++] = base + jj;
        }
        if (tid == 0) { int t = 0; for (int i = 0; i < 4; i++) t += s_warp[i]; s_tot = t; }
        __syncthreads();
        int tot = s_tot; if (tot > 64) tot = 64;
        if (tid >= tot && tid < 64) sel[tid] = sel[0];   // pad with first in-ball index
        __syncthreads();
        if (tid < 64) {
            int n = sel[tid];
            g_gi[cidx*64 + tid] = n;
            atomicAdd(&g_cnt[b*NPTS + n], 1);
        }
        __syncthreads();
    }
}

// ---------------- 3b) count-weighted stats of z0 ----------------
__global__ __launch_bounds__(256) void k_stat0() {
    __shared__ float red[512];
    int tid = threadIdx.x;
    int c = tid & 63, rg = tid >> 6;     // rg in 0..3
    int r0 = blockIdx.x * 256;
    float s1 = 0.f, s2 = 0.f;
    for (int r = r0 + rg; r < r0 + 256; r += 4) {
        float w = (float)g_cnt[r];
        float z = g_z0[r*64 + c];
        s1 += w*z; s2 += w*z*z;
    }
    red[tid] = s1; red[256 + tid] = s2;
    __syncthreads();
    if (tid < 64) {
        float a = red[tid] + red[tid+64] + red[tid+128] + red[tid+192];
        float b = red[256+tid] + red[256+tid+64] + red[256+tid+128] + red[256+tid+192];
        g_p0[blockIdx.x*128 + tid] = a;
        g_p0[blockIdx.x*128 + 64 + tid] = b;
    }
}

// ---------------- BN finalize on device-global partials (sel picks buffers) ----------
__global__ void k_fin(int sel, int nb,
                      const float* __restrict__ gm, const float* __restrict__ bt) {
    int c = threadIdx.x;
    const float* part; float* ab; int C;
    if (sel == 0)      { part = g_p0;   ab = g_ab0;  C = 64;  }
    else if (sel == 1) { part = g_p1;   ab = g_ab1;  C = 128; }
    else if (sel == 2) { part = g_pg0b; ab = g_abg0; C = 64;  }
    else               { part = g_pg1b; ab = g_abg1; C = 128; }
    float s1 = 0.f, s2 = 0.f;
    for (int r = 0; r < nb; r++) { s1 += part[r*2*C + c]; s2 += part[r*2*C + C + c]; }
    float m = s1 / MTOT;
    float v = s2 / MTOT - m*m;
    float a = gm[c] * rsqrtf(v + BNEPS);
    ab[c] = a; ab[C + c] = bt[c] - m*a;
}

// ---------------- partial reduce for geo layer1 stats (pg1 -> pg1b) ----------------
__global__ void k_red() {
    int c = threadIdx.x;               // 256
    float s = 0.f;
    int r0 = blockIdx.x * 64;
    for (int r = 0; r < 64; r++) s += g_pg1[(r0 + r)*256 + c];
    g_pg1b[blockIdx.x*256 + c] = s;
}

// ---------------- partial reduce for geo layer0 stats (pg0 -> pg0b) ----------------
__global__ void k_redg0() {
    int c = threadIdx.x;               // 128
    float s = 0.f;
    int r0 = blockIdx.x * 64;
    for (int r = 0; r < 64; r++) s += g_pg0[(r0 + r)*128 + c];
    g_pg0b[blockIdx.x*128 + c] = s;
}

// ---------------- 3c) h0 = relu(a0*z0+e0); z1 = h0 @ w1^T + b1 ----------------
// W pre-packed to u64 pairs at staging: main loop does broadcast LDS.64.
__global__ __launch_bounds__(256) void k_z1(const float* __restrict__ w1,
                                            const float* __restrict__ b1) {
    extern __shared__ float sm[];
    u64*   wsh64 = (u64*)sm;      // [c2][cc] stride 65 u64: 64*65*8 = 33280 B
    float* hsh   = sm + 8320;     // 64x68  [cc][swz(row)] = 17408 B
    __shared__ float a0[64], e0[64];
    int tid = threadIdx.x;
    if (tid < 64) { a0[tid] = g_ab0[tid]; e0[tid] = g_ab0[64 + tid]; }
    int row0 = blockIdx.x * 64;
    for (int idx = tid; idx < 4096; idx += 256) {
        int c2 = idx >> 6, cc = idx & 63;
        wsh64[c2*65 + cc] = pk(w1[(2*c2)*64 + cc], w1[(2*c2+1)*64 + cc]);
    }
    __syncthreads();
    for (int idx = tid; idx < 4096; idx += 256) {
        int r = idx >> 6, cc = idx & 63;
        float z = g_z0[(row0 + r)*64 + cc];
        hsh[cc*68 + swz(r)] = fmaxf(0.f, a0[cc]*z + e0[cc]);
    }
    __syncthreads();

    int rg = tid & 7;      // rows k = rg*8 + i
    int cg = tid >> 3;     // channels c = cg*4 + {0..3}
    int sw4 = (rg >> 2) << 2;
    const float* pLO = hsh + rg*8 + sw4;
    const float* pHI = hsh + rg*8 + (4 - sw4);
    const u64* pw64 = wsh64 + cg*2*65;
    u64 acc[8][2];
#pragma unroll
    for (int i = 0; i < 8; i++) { acc[i][0] = 0ull; acc[i][1] = 0ull; }
#pragma unroll 4
    for (int cc = 0; cc < 64; cc++) {
        float4 ha = *(const float4*)&pLO[cc*68];
        float4 hb = *(const float4*)&pHI[cc*68];
        u64 wp0 = pw64[cc];
        u64 wp1 = pw64[65 + cc];
        float hv[8] = {ha.x, ha.y, ha.z, ha.w, hb.x, hb.y, hb.z, hb.w};
#pragma unroll
        for (int i = 0; i < 8; i++) {
            u64 h2 = pk2(hv[i]);
            fma2(acc[i][0], h2, wp0);
            fma2(acc[i][1], h2, wp1);
        }
    }
#pragma unroll
    for (int i = 0; i < 8; i++) {
        int r = row0 + rg*8 + i, c = cg*4;
        float l0, h0v, l1, h1v;
        upk(l0, h0v, acc[i][0]); upk(l1, h1v, acc[i][1]);
        float4 v;
        v.x = l0 + b1[c];   v.y = h0v + b1[c+1];
        v.z = l1 + b1[c+2]; v.w = h1v + b1[c+3];
        *(float4*)&g_z1[r*128 + c] = v;
    }
}

// ---------------- 3d) count-weighted stats of z1 ----------------
__global__ __launch_bounds__(256) void k_stat1() {
    __shared__ float red[512];
    int tid = threadIdx.x;
    int c = tid & 127, rg = tid >> 7;   // rg in 0..1
    int r0 = blockIdx.x * 256;
    float s1 = 0.f, s2 = 0.f;
    for (int r = r0 + rg; r < r0 + 256; r += 2) {
        float w = (float)g_cnt[r];
        float z = g_z1[r*128 + c];
        s1 += w*z; s2 += w*z*z;
    }
    red[tid] = s1; red[256 + tid] = s2;
    __syncthreads();
    if (tid < 128) {
        g_p1[blockIdx.x*256 + tid]       = red[tid] + red[tid + 128];
        g_p1[blockIdx.x*256 + 128 + tid] = red[256 + tid] + red[256 + tid + 128];
    }
}

// ---------------- 4a) geo affine D[center] ----------------
__global__ __launch_bounds__(256) void k_D(const float* __restrict__ wg0) {
    __shared__ float v[192];
    int tid = threadIdx.x;
    if (tid < 192) { int c = tid/3, i = tid - 3*c; v[tid] = wg0[c*6 + 3 + i]; }
    __syncthreads();
    int s = blockIdx.x*4 + (tid >> 6), c = tid & 63;
    float x = g_cpos[s*3], y = g_cpos[s*3+1], z = g_cpos[s*3+2];
    g_D[s*64 + c] = v[c*3]*x + v[c*3+1]*y + v[c*3+2]*z;
}

// ---------------- 4b) geo layer0 pair stats (128 thr: even/odd cs halves) ----------
__global__ __launch_bounds__(128) void k_g0stats() {
    __shared__ float sS1[128], sS2[128];
    int tid = threadIdx.x;
    int c = tid & 63, half = tid >> 6;
    int b = blockIdx.x >> 6;
    int s0 = (blockIdx.x & 63) * 16;
    float S1 = 0.f, S2 = 0.f;
    for (int cs = half; cs < 16; cs += 2) {
        int cidx = b*NCTR + s0 + cs;
        const int* g = g_gi + cidx*64;
        float sA = 0.f, sA2 = 0.f;
#pragma unroll 8
        for (int k = 0; k < 64; k++) {
            int n = g[k];
            float a = g_A[(b*NPTS + n)*64 + c];
            sA += a; sA2 += a*a;
        }
        float d = g_D[cidx*64 + c];
        S1 += sA - 64.f*d;
        S2 += sA2 - 2.f*d*sA + 64.f*d*d;
    }
    sS1[tid] = S1; sS2[tid] = S2;
    __syncthreads();
    if (tid < 64) {
        g_pg0[blockIdx.x*128 + tid]      = sS1[tid] + sS1[64 + tid];
        g_pg0[blockIdx.x*128 + 64 + tid] = sS2[tid] + sS2[64 + tid];
    }
}

// ---------------- 5) big geo kernel (1 center / 128 thr, packed-u64 W) ----------
__global__ __launch_bounds__(128, 4) void k_geo(const float* __restrict__ wg1,
                                                const float* __restrict__ bg1) {
    extern __shared__ float sm[];
    u64*   wsh64 = (u64*)sm;              // [c2][cc] stride 65 u64 = 33280 B
    float* hsh   = sm + 8320;             // 64x68  [cc][swz(k)] = 17408 B
    __shared__ float dsh[64], a0[64], e0[64];
    int tid = threadIdx.x;
    int cidx = blockIdx.x;
    int b = cidx >> 10;
    for (int idx = tid; idx < 4096; idx += 128) {
        int c2 = idx >> 6, cc = idx & 63;
        wsh64[c2*65 + cc] = pk(wg1[(2*c2)*64 + cc], wg1[(2*c2+1)*64 + cc]);
    }
    if (tid < 64) {
        dsh[tid] = g_D[cidx*64 + tid];
        a0[tid] = g_abg0[tid];
        e0[tid] = g_abg0[64 + tid];
    }
    __syncthreads();
    for (int idx = tid; idx < 4096; idx += 128) {
        int k = idx >> 6, c = idx & 63;
        int n = g_gi[cidx*64 + k];
        float z = g_A[(b*NPTS + n)*64 + c] - dsh[c];
        hsh[c*68 + swz(k)] = fmaxf(0.f, a0[c]*z + e0[c]);
    }
    __syncthreads();

    int rg = tid & 7;      // rows k = rg*8 + i
    int cg = tid >> 3;     // ch   c = cg*8 + p*2 + {0,1}
    int sw4 = (rg >> 2) << 2;
    const float* pLO = hsh + rg*8 + sw4;
    const float* pHI = hsh + rg*8 + (4 - sw4);
    const u64* pw64 = wsh64 + cg*4*65;
    u64 acc[8][4];
#pragma unroll
    for (int i = 0; i < 8; i++)
#pragma unroll
        for (int p = 0; p < 4; p++) acc[i][p] = 0ull;
#pragma unroll 2
    for (int cc = 0; cc < 64; cc++) {
        float4 ha = *(const float4*)&pLO[cc*68];
        float4 hb = *(const float4*)&pHI[cc*68];
        u64 wp0 = pw64[cc];
        u64 wp1 = pw64[65 + cc];
        u64 wp2 = pw64[130 + cc];
        u64 wp3 = pw64[195 + cc];
        float hv[8] = {ha.x, ha.y, ha.z, ha.w, hb.x, hb.y, hb.z, hb.w};
#pragma unroll
        for (int i = 0; i < 8; i++) {
            u64 h2 = pk2(hv[i]);
            fma2(acc[i][0], h2, wp0);
            fma2(acc[i][1], h2, wp1);
            fma2(acc[i][2], h2, wp2);
            fma2(acc[i][3], h2, wp3);
        }
    }

    // epilogue, streamed per accumulator column p (two channels at a time)
#pragma unroll
    for (int p = 0; p < 4; p++) {
        float lo[8], hi[8];
#pragma unroll
        for (int i = 0; i < 8; i++) upk(lo[i], hi[i], acc[i][p]);
#pragma unroll
        for (int jj = 0; jj < 2; jj++) {
            int c = cg*8 + p*2 + jj;
            float bb = bg1[c];
            float mx = -FBIG, mn = FBIG, s1 = 0.f, s2 = 0.f;
#pragma unroll
            for (int i = 0; i < 8; i++) {
                float z = (jj ? hi[i] : lo[i]) + bb;
                mx = fmaxf(mx, z); mn = fminf(mn, z);
                s1 += z; s2 += z*z;
            }
#pragma unroll
            for (int o = 1; o < 8; o <<= 1) {
                mx = fmaxf(mx, __shfl_xor_sync(0xffffffffu, mx, o));
                mn = fminf(mn, __shfl_xor_sync(0xffffffffu, mn, o));
                s1 += __shfl_xor_sync(0xffffffffu, s1, o);
                s2 += __shfl_xor_sync(0xffffffffu, s2, o);
            }
            if (rg == 0) {
                g_zmx[cidx*128 + c] = mx;
                g_zmn[cidx*128 + c] = mn;
                g_pg1[cidx*256 + c] = s1;
                g_pg1[cidx*256 + 128 + c] = s2;
            }
        }
    }
}

// ---------------- 7a) semantic output: gather-max of pre-BN z1, monotone BN+relu ----
__global__ __launch_bounds__(128) void k_outsem(float* __restrict__ out) {
    int c = threadIdx.x;
    int cidx = blockIdx.x;
    int b = cidx >> 10;
    float a = g_ab1[c], e = g_ab1[128 + c];
    const int* g = g_gi + cidx*64;
    bool posa = (a >= 0.f);
    float m = posa ? -FBIG : FBIG;
#pragma unroll 4
    for (int k = 0; k < 64; k++) {
        int n = g[k];
        float z = g_z1[(b*NPTS + n)*128 + c];
        m = posa ? fmaxf(m, z) : fminf(m, z);
    }
    out[cidx*128 + c] = fmaxf(0.f, a*m + e);
}

// ---------------- 7b) geo output from zmax/zmin ----------------
__global__ __launch_bounds__(128) void k_outgeo(float* __restrict__ out) {
    int c = threadIdx.x;
    int cidx = blockIdx.x;
    float a = g_abg1[c], e = g_abg1[128 + c];
    float m = (a >= 0.f) ? g_zmx[cidx*128 + c] : g_zmn[cidx*128 + c];
    out[(BSC + cidx)*128 + c] = fmaxf(0.f, a*m + e);
}

// =============================== host ===============================
extern "C" void kernel_launch(void* const* d_in, const int* in_sizes, int n_in,
                              void* d_out, int out_size) {
    const float* pos  = (const float*)d_in[0];
    const float* feat = (const float*)d_in[1];
    const float* w0   = (const float*)d_in[2];
    const float* b0   = (const float*)d_in[3];
    const float* gm0  = (const float*)d_in[4];
    const float* bt0  = (const float*)d_in[5];
    const float* w1   = (const float*)d_in[6];
    const float* b1   = (const float*)d_in[7];
    const float* gm1  = (const float*)d_in[8];
    const float* bt1  = (const float*)d_in[9];
    const float* wg0  = (const float*)d_in[10];
    const float* bg0  = (const float*)d_in[11];
    const float* gmg0 = (const float*)d_in[12];
    const float* btg0 = (const float*)d_in[13];
    const float* wg1  = (const float*)d_in[14];
    const float* bg1  = (const float*)d_in[15];
    const float* gmg1 = (const float*)d_in[16];
    const float* btg1 = (const float*)d_in[17];
    float* out = (float*)d_out;

    cudaFuncSetAttribute(k_front, cudaFuncAttributeMaxDynamicSharedMemorySize, 49408);
    cudaFuncSetAttribute(k_group, cudaFuncAttributeMaxDynamicSharedMemorySize, 67840);
    cudaFuncSetAttribute(k_z1,    cudaFuncAttributeMaxDynamicSharedMemorySize, 50688);
    cudaFuncSetAttribute(k_geo,   cudaFuncAttributeMaxDynamicSharedMemorySize, 50688);

    k_zero<<<22, 1024>>>(0);                          // slot 1
    k_zero<<<22, 1024>>>(22528);                      // slot 2
    k_zero<<<20, 1024>>>(45056);                      // slot 3
    k_front<<<16 + 1024 + 8192, 512, 49408>>>(pos, feat, w0, b0, wg0, bg0);  // slot 4 -> ncu
    k_D<<<BSC/4, 256>>>(wg0);
    k_group<<<dim3(64, NBATCH), 128, 67840>>>(pos);

    // semantic branch
    k_stat0<<<256, 256>>>();
    k_fin<<<1, 64>>>(0, 256, gm0, bt0);
    k_z1<<<BNP/64, 256, 50688>>>(w1, b1);
    k_stat1<<<256, 256>>>();
    k_fin<<<1, 128>>>(1, 256, gm1, bt1);

    // geo branch
    k_g0stats<<<1024, 128>>>();
    k_redg0<<<16, 128>>>();
    k_fin<<<1, 64>>>(2, 16, gmg0, btg0);
    k_geo<<<BSC, 128, 50688>>>(wg1, bg1);
    k_red<<<256, 256>>>();
    k_fin<<<1, 128>>>(3, 256, gmg1, btg1);

    // outputs
    k_outsem<<<BSC, 128>>>(out);
    k_outgeo<<<BSC, 128>>>(out);
    (void)in_sizes; (void)n_in; (void)out_size;
}